// round 13
// baseline (speedup 1.0000x reference)
#include <cuda_runtime.h>
#include <cstdint>
#include <cmath>

// ---------------- problem constants ----------------
#define Bv      8
#define NTOK    1024
#define Cdim    384
#define Hh      6
#define Dh      64
#define Mtok    1026            // N_TOK + CLS + pad
#define Ntok1   1025            // N_TOK + CLS
#define WWIN    256
#define HID     1536
#define SCALE   0.40824829046386307f   // 6^-0.5
#define EPSLN   1e-5f

// ---------------- scratch (static device globals; no allocation) ----------------
__device__ float g_h    [Bv * Mtok  * Cdim];
__device__ float g_qkv  [Bv * Mtok  * 3 * Cdim];
__device__ float g_attn [Bv * Ntok1 * Cdim];
__device__ float g_h2   [Bv * Ntok1 * Cdim];
__device__ float g_h2n  [Bv * Ntok1 * Cdim];
__device__ float g_h3   [Bv * 257   * Cdim];
__device__ float g_h3n  [Bv * 257   * Cdim];
__device__ float g_fc1  [Bv * 257   * HID];

// ---------------- tf32 helpers ----------------
__device__ __forceinline__ float to_tf32(float x) {
    float y; asm("cvt.rna.tf32.f32 %0, %1;" : "=f"(y) : "f"(x)); return y;
}
__device__ __forceinline__ void mma_tf32(float* c, const uint32_t* a, const uint32_t* b) {
    asm volatile(
        "mma.sync.aligned.m16n8k8.row.col.f32.tf32.tf32.f32 "
        "{%0,%1,%2,%3}, {%4,%5,%6,%7}, {%8,%9}, {%0,%1,%2,%3};"
        : "+f"(c[0]), "+f"(c[1]), "+f"(c[2]), "+f"(c[3])
        : "r"(a[0]), "r"(a[1]), "r"(a[2]), "r"(a[3]), "r"(b[0]), "r"(b[1]));
}
__device__ __forceinline__ float gelu(float v) {
    return 0.5f * v * (1.f + erff(v * 0.70710678118654752f));
}

#define SSTR 36
#define PANEL_F (128 * SSTR)

// ============ 128x128 tf32 mma GEMM: C = A @ W^T (+bias)(+gelu)(+residual) ============
// 8 warps (2m x 4n), warp tile 64x32. K-panel 32, double-buffered smem.
// RES: residual source with Mtok row stride (padded layout), row map b*1026+m.
template <int ACT, int RES>
__global__ void __launch_bounds__(256)
gemm_mma(const float* __restrict__ A, const float* __restrict__ W,
         const float* __restrict__ bias, float* __restrict__ Cm,
         const float* __restrict__ Res, int Mr, int Nc, int Kd) {
    extern __shared__ __align__(16) float smem[];
    const int tid = threadIdx.x;
    const int wid = tid >> 5, lane = tid & 31;
    const int g = lane >> 2, t = lane & 3;
    const int wm = wid & 1, wn = wid >> 1;
    const int m0 = blockIdx.y * 128, n0 = blockIdx.x * 128;
    const int ldrow = tid >> 3, ldq = tid & 7;

    float acc[4][4][4];
    #pragma unroll
    for (int i = 0; i < 4; i++)
        #pragma unroll
        for (int j = 0; j < 4; j++)
            #pragma unroll
            for (int k = 0; k < 4; k++) acc[i][j][k] = 0.f;

    const int P = Kd >> 5;
    float4 ra[4], rb[4];

    auto ldg = [&](int p) {
        #pragma unroll
        for (int k = 0; k < 4; k++) {
            int row = ldrow + 32 * k;
            int gr = m0 + row;
            ra[k] = (gr < Mr) ? *(const float4*)(A + (size_t)gr * Kd + p * 32 + ldq * 4)
                              : make_float4(0.f, 0.f, 0.f, 0.f);
            rb[k] = *(const float4*)(W + (size_t)(n0 + row) * Kd + p * 32 + ldq * 4);
        }
    };
    auto sts = [&](int b) {
        float* Ab = smem + b * PANEL_F;
        float* Bb = smem + 2 * PANEL_F + b * PANEL_F;
        #pragma unroll
        for (int k = 0; k < 4; k++) {
            int row = ldrow + 32 * k;
            float4 va = ra[k], vb = rb[k];
            va.x = to_tf32(va.x); va.y = to_tf32(va.y); va.z = to_tf32(va.z); va.w = to_tf32(va.w);
            vb.x = to_tf32(vb.x); vb.y = to_tf32(vb.y); vb.z = to_tf32(vb.z); vb.w = to_tf32(vb.w);
            *(float4*)(Ab + row * SSTR + ldq * 4) = va;
            *(float4*)(Bb + row * SSTR + ldq * 4) = vb;
        }
    };
    auto compute = [&](int b) {
        const float* Ab = smem + b * PANEL_F;
        const float* Bb = smem + 2 * PANEL_F + b * PANEL_F;
        #pragma unroll
        for (int kk = 0; kk < 4; kk++) {
            uint32_t af[4][4];
            #pragma unroll
            for (int ma = 0; ma < 4; ma++) {
                const float* p = Ab + (wm * 64 + ma * 16 + g) * SSTR + kk * 8 + t;
                af[ma][0] = __float_as_uint(p[0]);
                af[ma][1] = __float_as_uint(p[8 * SSTR]);
                af[ma][2] = __float_as_uint(p[4]);
                af[ma][3] = __float_as_uint(p[8 * SSTR + 4]);
            }
            uint32_t bf[4][2];
            #pragma unroll
            for (int na = 0; na < 4; na++) {
                const float* p = Bb + (wn * 32 + na * 8 + g) * SSTR + kk * 8 + t;
                bf[na][0] = __float_as_uint(p[0]);
                bf[na][1] = __float_as_uint(p[4]);
            }
            #pragma unroll
            for (int ma = 0; ma < 4; ma++)
                #pragma unroll
                for (int na = 0; na < 4; na++)
                    mma_tf32(acc[ma][na], af[ma], bf[na]);
        }
    };

    ldg(0);
    sts(0);
    __syncthreads();
    for (int p = 0; p < P; p++) {
        int b = p & 1;
        if (p + 1 < P) ldg(p + 1);
        compute(b);
        __syncthreads();
        if (p + 1 < P) { sts(b ^ 1); __syncthreads(); }
    }

    #pragma unroll
    for (int ma = 0; ma < 4; ma++) {
        int row = m0 + wm * 64 + ma * 16 + g;
        #pragma unroll
        for (int na = 0; na < 4; na++) {
            int col = n0 + wn * 32 + na * 8 + 2 * t;
            float b0 = 0.f, b1 = 0.f;
            if (bias) { b0 = bias[col]; b1 = bias[col + 1]; }
            float v0 = acc[ma][na][0] + b0, v1 = acc[ma][na][1] + b1;
            float v2 = acc[ma][na][2] + b0, v3 = acc[ma][na][3] + b1;
            if (ACT) { v0 = gelu(v0); v1 = gelu(v1); v2 = gelu(v2); v3 = gelu(v3); }
            if (row < Mr) {
                if (RES) {
                    size_t ri = ((size_t)(row / Ntok1) * Mtok + row % Ntok1) * Cdim + col;
                    v0 += Res[ri]; v1 += Res[ri + 1];
                }
                *(float2*)(Cm + (size_t)row * Nc + col) = make_float2(v0, v1);
            }
            if (row + 8 < Mr) {
                if (RES) {
                    size_t ri = ((size_t)((row + 8) / Ntok1) * Mtok + (row + 8) % Ntok1) * Cdim + col;
                    v2 += Res[ri]; v3 += Res[ri + 1];
                }
                *(float2*)(Cm + (size_t)(row + 8) * Nc + col) = make_float2(v2, v3);
            }
        }
    }
}

// ============ 64x64 tf32 mma GEMM (more blocks for deep-K / narrow-N GEMMs) ============
// 4 warps (2m x 2n), warp tile 32x32.
// GATHER: A is g_h2n; row = window slot, col = j*384+c (analytic 3x3 stride-2 gather).
// H3MAP:  C row bw -> g_h3 row (bw>>8)*257 + 1 + (bw&255).
#define PANEL64 (64 * SSTR)
template <int GATHER, int H3MAP>
__global__ void __launch_bounds__(128)
gemm_mma64(const float* __restrict__ A, const float* __restrict__ W,
           const float* __restrict__ bias, float* __restrict__ Cm,
           int Mr, int Nc, int Kd) {
    __shared__ __align__(16) float smem[4 * PANEL64];
    const int tid = threadIdx.x;
    const int wid = tid >> 5, lane = tid & 31;
    const int g = lane >> 2, t = lane & 3;
    const int wm = wid & 1, wn = wid >> 1;
    const int m0 = blockIdx.y * 64, n0 = blockIdx.x * 64;
    const int ldrow = tid >> 3, ldq = tid & 7;

    float acc[2][4][4];
    #pragma unroll
    for (int i = 0; i < 2; i++)
        #pragma unroll
        for (int j = 0; j < 4; j++)
            #pragma unroll
            for (int k = 0; k < 4; k++) acc[i][j][k] = 0.f;

    const int P = Kd >> 5;
    float4 ra[4], rb[4];

    auto ldg = [&](int p) {
        #pragma unroll
        for (int k = 0; k < 4; k++) {
            int row = ldrow + 16 * k;
            int gr = m0 + row;
            if (GATHER) {
                // gr in [0,2048): b=gr>>8, window w=gr&255; panel -> (j, c)
                int b = gr >> 8, w = gr & 255;
                int wy = w >> 4, wx = w & 15;
                int j = p / 12;
                int c = (p % 12) * 32 + ldq * 4;
                int dy = j / 3 - 1, dx = j % 3 - 1;
                int rp = 2 * wy + dy, cp = 2 * wx + dx;
                int src = ((unsigned)rp < 32u && (unsigned)cp < 32u) ? (1 + rp * 32 + cp) : 1024;
                ra[k] = *(const float4*)(A + ((size_t)b * Ntok1 + src) * Cdim + c);
            } else {
                ra[k] = (gr < Mr) ? *(const float4*)(A + (size_t)gr * Kd + p * 32 + ldq * 4)
                                  : make_float4(0.f, 0.f, 0.f, 0.f);
            }
            rb[k] = *(const float4*)(W + (size_t)(n0 + row) * Kd + p * 32 + ldq * 4);
        }
    };
    auto sts = [&](int b) {
        float* Ab = smem + b * PANEL64;
        float* Bb = smem + 2 * PANEL64 + b * PANEL64;
        #pragma unroll
        for (int k = 0; k < 4; k++) {
            int row = ldrow + 16 * k;
            float4 va = ra[k], vb = rb[k];
            va.x = to_tf32(va.x); va.y = to_tf32(va.y); va.z = to_tf32(va.z); va.w = to_tf32(va.w);
            vb.x = to_tf32(vb.x); vb.y = to_tf32(vb.y); vb.z = to_tf32(vb.z); vb.w = to_tf32(vb.w);
            *(float4*)(Ab + row * SSTR + ldq * 4) = va;
            *(float4*)(Bb + row * SSTR + ldq * 4) = vb;
        }
    };
    auto compute = [&](int b) {
        const float* Ab = smem + b * PANEL64;
        const float* Bb = smem + 2 * PANEL64 + b * PANEL64;
        #pragma unroll
        for (int kk = 0; kk < 4; kk++) {
            uint32_t af[2][4];
            #pragma unroll
            for (int ma = 0; ma < 2; ma++) {
                const float* p = Ab + (wm * 32 + ma * 16 + g) * SSTR + kk * 8 + t;
                af[ma][0] = __float_as_uint(p[0]);
                af[ma][1] = __float_as_uint(p[8 * SSTR]);
                af[ma][2] = __float_as_uint(p[4]);
                af[ma][3] = __float_as_uint(p[8 * SSTR + 4]);
            }
            uint32_t bf[4][2];
            #pragma unroll
            for (int na = 0; na < 4; na++) {
                const float* p = Bb + (wn * 32 + na * 8 + g) * SSTR + kk * 8 + t;
                bf[na][0] = __float_as_uint(p[0]);
                bf[na][1] = __float_as_uint(p[4]);
            }
            #pragma unroll
            for (int ma = 0; ma < 2; ma++)
                #pragma unroll
                for (int na = 0; na < 4; na++)
                    mma_tf32(acc[ma][na], af[ma], bf[na]);
        }
    };

    ldg(0);
    sts(0);
    __syncthreads();
    for (int p = 0; p < P; p++) {
        int b = p & 1;
        if (p + 1 < P) ldg(p + 1);
        compute(b);
        __syncthreads();
        if (p + 1 < P) { sts(b ^ 1); __syncthreads(); }
    }

    #pragma unroll
    for (int ma = 0; ma < 2; ma++) {
        int row = m0 + wm * 32 + ma * 16 + g;
        #pragma unroll
        for (int na = 0; na < 4; na++) {
            int col = n0 + wn * 32 + na * 8 + 2 * t;
            float b0 = 0.f, b1 = 0.f;
            if (bias) { b0 = bias[col]; b1 = bias[col + 1]; }
            float v0 = acc[ma][na][0] + b0, v1 = acc[ma][na][1] + b1;
            float v2 = acc[ma][na][2] + b0, v3 = acc[ma][na][3] + b1;
            int r0 = row, r1 = row + 8;
            if (H3MAP) {
                int o0 = (r0 >> 8) * 257 + 1 + (r0 & 255);
                int o1 = (r1 >> 8) * 257 + 1 + (r1 & 255);
                *(float2*)(Cm + (size_t)o0 * Nc + col) = make_float2(v0, v1);
                *(float2*)(Cm + (size_t)o1 * Nc + col) = make_float2(v2, v3);
            } else {
                if (r0 < Mr) *(float2*)(Cm + (size_t)r0 * Nc + col) = make_float2(v0, v1);
                if (r1 < Mr) *(float2*)(Cm + (size_t)r1 * Nc + col) = make_float2(v2, v3);
            }
        }
    }
}

// ---------------- block reduce helper ----------------
__device__ __forceinline__ float block_reduce_sum128(float v, float* sh) {
    #pragma unroll
    for (int o = 16; o; o >>= 1) v += __shfl_xor_sync(0xffffffffu, v, o);
    int w = threadIdx.x >> 5;
    if ((threadIdx.x & 31) == 0) sh[w] = v;
    __syncthreads();
    v = sh[0] + sh[1] + sh[2] + sh[3];
    __syncthreads();
    return v;
}

__device__ __forceinline__ bool axis_ok(int a, int b) {
    int lo = max(max(a, b) - 1, 0);
    int hi = min(min(a, b) + 1, 30);
    if (lo > hi) return false;
    return ((lo & 1) == 0) || (lo + 1 <= hi);
}

// ---------------- LN1 with zero-pad row ----------------
__global__ void ln1_pad_kernel(const float* __restrict__ x,
                               const float* __restrict__ w,
                               const float* __restrict__ b) {
    __shared__ float sh[4];
    int r = blockIdx.x;
    int bb = r / Mtok, m = r % Mtok;
    int t = threadIdx.x;
    float* out = g_h + (size_t)r * Cdim;
    if (m == Ntok1) {
        out[t] = 0.f; out[t + 128] = 0.f; out[t + 256] = 0.f;
        return;
    }
    const float* xr = x + ((size_t)bb * Ntok1 + m) * Cdim;
    float v0 = xr[t], v1 = xr[t + 128], v2 = xr[t + 256];
    float mu = block_reduce_sum128(v0 + v1 + v2, sh) * (1.f / Cdim);
    float d0 = v0 - mu, d1 = v1 - mu, d2 = v2 - mu;
    float var = block_reduce_sum128(d0 * d0 + d1 * d1 + d2 * d2, sh) * (1.f / Cdim);
    float rs = rsqrtf(var + EPSLN);
    out[t]       = d0 * rs * w[t]       + b[t];
    out[t + 128] = d1 * rs * w[t + 128] + b[t + 128];
    out[t + 256] = d2 * rs * w[t + 256] + b[t + 256];
}

// ---------------- generic LN ----------------
__global__ void ln_kernel(const float* __restrict__ in,
                          const float* __restrict__ w,
                          const float* __restrict__ b,
                          float* __restrict__ out) {
    __shared__ float sh[4];
    int r = blockIdx.x, t = threadIdx.x;
    const float* xr = in + (size_t)r * Cdim;
    float v0 = xr[t], v1 = xr[t + 128], v2 = xr[t + 256];
    float mu = block_reduce_sum128(v0 + v1 + v2, sh) * (1.f / Cdim);
    float d0 = v0 - mu, d1 = v1 - mu, d2 = v2 - mu;
    float var = block_reduce_sum128(d0 * d0 + d1 * d1 + d2 * d2, sh) * (1.f / Cdim);
    float rs = rsqrtf(var + EPSLN);
    float* o = out + (size_t)r * Cdim;
    o[t]       = d0 * rs * w[t]       + b[t];
    o[t + 128] = d1 * rs * w[t + 128] + b[t + 128];
    o[t + 256] = d2 * rs * w[t + 256] + b[t + 256];
}

// ---------------- sparse attention (image queries), two-phase exact softmax ----------------
// grid: (1024, Bv), block: 192 (6 warps = 6 heads)
__global__ void attn_sparse_kernel() {
    int m = blockIdx.x + 1;
    int b = blockIdx.y;
    int h = threadIdx.x >> 5;
    int lane = threadIdx.x & 31;
    const float* base = g_qkv + (size_t)b * Mtok * (3 * Cdim);
    const float* qrow = base + (size_t)m * (3 * Cdim) + h * Dh;
    float q0 = qrow[lane] * SCALE, q1 = qrow[lane + 32] * SCALE;

    int i = m - 1, r = i >> 5, c = i & 31;
    bool okr[5], okc[5];
    #pragma unroll
    for (int d = 0; d < 5; d++) {
        int rp = r + d - 2, cp = c + d - 2;
        okr[d] = ((unsigned)rp < 32u) && axis_ok(r, rp);
        okc[d] = ((unsigned)cp < 32u) && axis_ok(c, cp);
    }

    auto score = [&](int kidx) {
        const float* kr = base + (size_t)kidx * (3 * Cdim) + Cdim + h * Dh;
        float s = q0 * kr[lane] + q1 * kr[lane + 32];
        #pragma unroll
        for (int o = 16; o; o >>= 1) s += __shfl_xor_sync(0xffffffffu, s, o);
        return s;
    };

    // phase 1: all scores, exact max (pad key contributes score 0)
    float s[26];
    s[0] = score(0);                       // CLS
    float mx = fmaxf(s[0], 0.f);
    #pragma unroll
    for (int u = 0; u < 25; u++) {
        int dr = u / 5, dc = u % 5;
        bool ok = okr[dr] && okc[dc];
        if (ok) {
            int kidx = 1 + (r + dr - 2) * 32 + (c + dc - 2);
            s[u + 1] = score(kidx);
            mx = fmaxf(mx, s[u + 1]);
        } else {
            s[u + 1] = -1e30f;
        }
    }

    // phase 2: single exp per key, accumulate
    float l = __expf(0.f - mx);            // pad key (v == 0)
    float a0 = 0.f, a1 = 0.f;
    {
        float p = __expf(s[0] - mx);
        const float* vr = base + 2 * Cdim + h * Dh;   // key 0
        a0 += p * vr[lane]; a1 += p * vr[lane + 32]; l += p;
    }
    #pragma unroll
    for (int u = 0; u < 25; u++) {
        int dr = u / 5, dc = u % 5;
        if (okr[dr] && okc[dc]) {
            int kidx = 1 + (r + dr - 2) * 32 + (c + dc - 2);
            float p = __expf(s[u + 1] - mx);
            const float* vr = base + (size_t)kidx * (3 * Cdim) + 2 * Cdim + h * Dh;
            a0 += p * vr[lane]; a1 += p * vr[lane + 32]; l += p;
        }
    }
    float inv = 1.f / l;
    float* o = g_attn + ((size_t)(b * Ntok1 + m)) * Cdim + h * Dh;
    o[lane] = a0 * inv;
    o[lane + 32] = a1 * inv;
}

// ---------------- dense attention for CLS query ----------------
__global__ void attn_cls_kernel() {
    __shared__ float sc[Mtok];
    __shared__ float qs[Dh];
    __shared__ float red[8];
    __shared__ float accsh[256];
    int h = blockIdx.x, b = blockIdx.y;
    int tid = threadIdx.x;
    const float* base = g_qkv + (size_t)b * Mtok * (3 * Cdim);
    if (tid < Dh) qs[tid] = base[h * Dh + tid] * SCALE;
    __syncthreads();

    float lmax = -1e30f;
    for (int k = tid; k < Ntok1; k += 256) {
        const float* kr = base + (size_t)k * (3 * Cdim) + Cdim + h * Dh;
        float s = 0.f;
        #pragma unroll
        for (int d = 0; d < Dh; d++) s += qs[d] * kr[d];
        sc[k] = s;
        lmax = fmaxf(lmax, s);
    }
    if (tid == 0) sc[Ntok1] = 0.f;
    lmax = fmaxf(lmax, 0.f);
    #pragma unroll
    for (int o = 16; o; o >>= 1) lmax = fmaxf(lmax, __shfl_xor_sync(0xffffffffu, lmax, o));
    if ((tid & 31) == 0) red[tid >> 5] = lmax;
    __syncthreads();
    float mx = red[0];
    #pragma unroll
    for (int w = 1; w < 8; w++) mx = fmaxf(mx, red[w]);
    __syncthreads();

    float lsum = 0.f;
    for (int k = tid; k < Mtok; k += 256) {
        float p = __expf(sc[k] - mx);
        sc[k] = p;
        lsum += p;
    }
    #pragma unroll
    for (int o = 16; o; o >>= 1) lsum += __shfl_xor_sync(0xffffffffu, lsum, o);
    if ((tid & 31) == 0) red[tid >> 5] = lsum;
    __syncthreads();
    float Z = red[0] + red[1] + red[2] + red[3] + red[4] + red[5] + red[6] + red[7];

    int d = tid & 63, ks = tid >> 6;
    float acc = 0.f;
    for (int k = ks; k < Ntok1; k += 4)
        acc += sc[k] * base[(size_t)k * (3 * Cdim) + 2 * Cdim + h * Dh + d];
    accsh[tid] = acc;
    __syncthreads();
    if (tid < 64) {
        float o = accsh[tid] + accsh[64 + tid] + accsh[128 + tid] + accsh[192 + tid];
        g_attn[((size_t)(b * Ntok1)) * Cdim + h * Dh + tid] = o / Z;
    }
}

// ---------------- CLS row copy into g_h3 row 0 of each batch ----------------
__global__ void cls_copy_kernel() {
    int b = blockIdx.x, t = threadIdx.x;
    g_h3[(size_t)b * 257 * Cdim + t] = g_h2n[(size_t)b * Ntok1 * Cdim + t];
}

// ---------------- launch ----------------
extern "C" void kernel_launch(void* const* d_in, const int* in_sizes, int n_in,
                              void* d_out, int out_size) {
    const float* x       = (const float*)d_in[0];
    const float* norm1_w = (const float*)d_in[1];
    const float* norm1_b = (const float*)d_in[2];
    const float* qkv_w   = (const float*)d_in[3];
    const float* proj_w  = (const float*)d_in[4];
    const float* proj_b  = (const float*)d_in[5];
    const float* norm2_w = (const float*)d_in[6];
    const float* norm2_b = (const float*)d_in[7];
    const float* pool_w  = (const float*)d_in[8];
    const float* pool_b  = (const float*)d_in[9];
    const float* norm3_w = (const float*)d_in[10];
    const float* norm3_b = (const float*)d_in[11];
    const float* fc1_w   = (const float*)d_in[12];
    const float* fc1_b   = (const float*)d_in[13];
    const float* fc2_w   = (const float*)d_in[14];
    const float* fc2_b   = (const float*)d_in[15];
    float* out = (float*)d_out;

    float *p_h, *p_qkv, *p_attn, *p_h2, *p_h2n, *p_h3, *p_h3n, *p_fc1;
    cudaGetSymbolAddress((void**)&p_h,    g_h);
    cudaGetSymbolAddress((void**)&p_qkv,  g_qkv);
    cudaGetSymbolAddress((void**)&p_attn, g_attn);
    cudaGetSymbolAddress((void**)&p_h2,   g_h2);
    cudaGetSymbolAddress((void**)&p_h2n,  g_h2n);
    cudaGetSymbolAddress((void**)&p_h3,   g_h3);
    cudaGetSymbolAddress((void**)&p_h3n,  g_h3n);
    cudaGetSymbolAddress((void**)&p_fc1,  g_fc1);

    const int SMEMB = 4 * PANEL_F * sizeof(float);   // 73728 B
    cudaFuncSetAttribute(gemm_mma<0, 0>, cudaFuncAttributeMaxDynamicSharedMemorySize, SMEMB);
    cudaFuncSetAttribute(gemm_mma<0, 1>, cudaFuncAttributeMaxDynamicSharedMemorySize, SMEMB);
    cudaFuncSetAttribute(gemm_mma<1, 0>, cudaFuncAttributeMaxDynamicSharedMemorySize, SMEMB);

    // 1) LN1 + zero-pad
    ln1_pad_kernel<<<Bv * Mtok, 128>>>(x, norm1_w, norm1_b);
    // 2) QKV GEMM: (8208 x 384) @ (384 x 1152)
    gemm_mma<0, 0><<<dim3(1152 / 128, (Bv * Mtok + 127) / 128), 256, SMEMB>>>(
        p_h, qkv_w, nullptr, p_qkv, nullptr, Bv * Mtok, 3 * Cdim, Cdim);
    // 3) attention
    attn_cls_kernel<<<dim3(Hh, Bv), 256>>>();
    attn_sparse_kernel<<<dim3(NTOK, Bv), 192>>>();
    // 4) proj GEMM + fused residual add
    gemm_mma<0, 1><<<dim3(Cdim / 128, (Bv * Ntok1 + 127) / 128), 256, SMEMB>>>(
        p_attn, proj_w, proj_b, p_h2, p_h, Bv * Ntok1, Cdim, Cdim);
    // 5) LN2
    ln_kernel<<<Bv * Ntok1, 128>>>(p_h2, norm2_w, norm2_b, p_h2n);
    // 6) pool GEMM with fused gather + fused concat placement:
    //    (2048 x 3456 gathered from h2n) @ (3456 x 384) -> g_h3 rows 1..256
    gemm_mma64<1, 1><<<dim3(Cdim / 64, (Bv * WWIN) / 64), 128>>>(
        p_h2n, pool_w, pool_b, p_h3, Bv * WWIN, Cdim, 9 * Cdim);
    cls_copy_kernel<<<Bv, Cdim>>>();
    // 7) LN3
    ln_kernel<<<Bv * 257, 128>>>(p_h3, norm3_w, norm3_b, p_h3n);
    // 8) MLP
    gemm_mma<1, 0><<<dim3(HID / 128, (Bv * 257 + 127) / 128), 256, SMEMB>>>(
        p_h3n, fc1_w, fc1_b, p_fc1, nullptr, Bv * 257, HID, Cdim);
    gemm_mma64<0, 0><<<dim3(Cdim / 64, (Bv * 257 + 63) / 64), 128>>>(
        p_fc1, fc2_w, fc2_b, out, Bv * 257, Cdim, HID);
}

// round 16
// speedup vs baseline: 1.2453x; 1.2453x over previous
#include <cuda_runtime.h>
#include <cstdint>
#include <cmath>

// ---------------- problem constants ----------------
#define Bv      8
#define NTOK    1024
#define Cdim    384
#define Hh      6
#define Dh      64
#define Mtok    1026            // N_TOK + CLS + pad
#define Ntok1   1025            // N_TOK + CLS
#define WWIN    256
#define HID     1536
#define SCALE   0.40824829046386307f   // 6^-0.5
#define EPSLN   1e-5f

// ---------------- scratch (static device globals; no allocation) ----------------
__device__ float g_h    [Bv * Mtok  * Cdim];
__device__ float g_qkv  [Bv * Mtok  * 3 * Cdim];
__device__ float g_attn [Bv * Ntok1 * Cdim];
__device__ float g_h2   [Bv * Ntok1 * Cdim];
__device__ float g_h2n  [Bv * Ntok1 * Cdim];
__device__ float g_h3   [Bv * 257   * Cdim];
__device__ float g_h3n  [Bv * 257   * Cdim];
__device__ float g_fc1  [Bv * 257   * HID];

// ---------------- tf32 helpers ----------------
__device__ __forceinline__ float to_tf32(float x) {
    float y; asm("cvt.rna.tf32.f32 %0, %1;" : "=f"(y) : "f"(x)); return y;
}
__device__ __forceinline__ void mma_tf32(float* c, const uint32_t* a, const uint32_t* b) {
    asm volatile(
        "mma.sync.aligned.m16n8k8.row.col.f32.tf32.tf32.f32 "
        "{%0,%1,%2,%3}, {%4,%5,%6,%7}, {%8,%9}, {%0,%1,%2,%3};"
        : "+f"(c[0]), "+f"(c[1]), "+f"(c[2]), "+f"(c[3])
        : "r"(a[0]), "r"(a[1]), "r"(a[2]), "r"(a[3]), "r"(b[0]), "r"(b[1]));
}
__device__ __forceinline__ float gelu(float v) {
    return 0.5f * v * (1.f + erff(v * 0.70710678118654752f));
}

#define SSTR 36
#define PANEL_F (128 * SSTR)

// ============ 128x128 tf32 mma GEMM: C = A @ W^T (+bias)(+gelu)(+residual) ============
// 8 warps (2m x 4n), warp tile 64x32. K-panel 32, double-buffered smem.
// RES: residual source with Mtok row stride (padded layout), row map b*1026+m.
template <int ACT, int RES>
__global__ void __launch_bounds__(256)
gemm_mma(const float* __restrict__ A, const float* __restrict__ W,
         const float* __restrict__ bias, float* __restrict__ Cm,
         const float* __restrict__ Res, int Mr, int Nc, int Kd) {
    extern __shared__ __align__(16) float smem[];
    const int tid = threadIdx.x;
    const int wid = tid >> 5, lane = tid & 31;
    const int g = lane >> 2, t = lane & 3;
    const int wm = wid & 1, wn = wid >> 1;
    const int m0 = blockIdx.y * 128, n0 = blockIdx.x * 128;
    const int ldrow = tid >> 3, ldq = tid & 7;

    float acc[4][4][4];
    #pragma unroll
    for (int i = 0; i < 4; i++)
        #pragma unroll
        for (int j = 0; j < 4; j++)
            #pragma unroll
            for (int k = 0; k < 4; k++) acc[i][j][k] = 0.f;

    const int P = Kd >> 5;
    float4 ra[4], rb[4];

    auto ldg = [&](int p) {
        #pragma unroll
        for (int k = 0; k < 4; k++) {
            int row = ldrow + 32 * k;
            int gr = m0 + row;
            ra[k] = (gr < Mr) ? *(const float4*)(A + (size_t)gr * Kd + p * 32 + ldq * 4)
                              : make_float4(0.f, 0.f, 0.f, 0.f);
            rb[k] = *(const float4*)(W + (size_t)(n0 + row) * Kd + p * 32 + ldq * 4);
        }
    };
    auto sts = [&](int b) {
        float* Ab = smem + b * PANEL_F;
        float* Bb = smem + 2 * PANEL_F + b * PANEL_F;
        #pragma unroll
        for (int k = 0; k < 4; k++) {
            int row = ldrow + 32 * k;
            float4 va = ra[k], vb = rb[k];
            va.x = to_tf32(va.x); va.y = to_tf32(va.y); va.z = to_tf32(va.z); va.w = to_tf32(va.w);
            vb.x = to_tf32(vb.x); vb.y = to_tf32(vb.y); vb.z = to_tf32(vb.z); vb.w = to_tf32(vb.w);
            *(float4*)(Ab + row * SSTR + ldq * 4) = va;
            *(float4*)(Bb + row * SSTR + ldq * 4) = vb;
        }
    };
    auto compute = [&](int b) {
        const float* Ab = smem + b * PANEL_F;
        const float* Bb = smem + 2 * PANEL_F + b * PANEL_F;
        #pragma unroll
        for (int kk = 0; kk < 4; kk++) {
            uint32_t af[4][4];
            #pragma unroll
            for (int ma = 0; ma < 4; ma++) {
                const float* p = Ab + (wm * 64 + ma * 16 + g) * SSTR + kk * 8 + t;
                af[ma][0] = __float_as_uint(p[0]);
                af[ma][1] = __float_as_uint(p[8 * SSTR]);
                af[ma][2] = __float_as_uint(p[4]);
                af[ma][3] = __float_as_uint(p[8 * SSTR + 4]);
            }
            uint32_t bf[4][2];
            #pragma unroll
            for (int na = 0; na < 4; na++) {
                const float* p = Bb + (wn * 32 + na * 8 + g) * SSTR + kk * 8 + t;
                bf[na][0] = __float_as_uint(p[0]);
                bf[na][1] = __float_as_uint(p[4]);
            }
            #pragma unroll
            for (int ma = 0; ma < 4; ma++)
                #pragma unroll
                for (int na = 0; na < 4; na++)
                    mma_tf32(acc[ma][na], af[ma], bf[na]);
        }
    };

    ldg(0);
    sts(0);
    __syncthreads();
    for (int p = 0; p < P; p++) {
        int b = p & 1;
        if (p + 1 < P) ldg(p + 1);
        compute(b);
        __syncthreads();
        if (p + 1 < P) { sts(b ^ 1); __syncthreads(); }
    }

    #pragma unroll
    for (int ma = 0; ma < 4; ma++) {
        int row = m0 + wm * 64 + ma * 16 + g;
        #pragma unroll
        for (int na = 0; na < 4; na++) {
            int col = n0 + wn * 32 + na * 8 + 2 * t;
            float b0 = 0.f, b1 = 0.f;
            if (bias) { b0 = bias[col]; b1 = bias[col + 1]; }
            float v0 = acc[ma][na][0] + b0, v1 = acc[ma][na][1] + b1;
            float v2 = acc[ma][na][2] + b0, v3 = acc[ma][na][3] + b1;
            if (ACT) { v0 = gelu(v0); v1 = gelu(v1); v2 = gelu(v2); v3 = gelu(v3); }
            if (row < Mr) {
                if (RES) {
                    size_t ri = ((size_t)(row / Ntok1) * Mtok + row % Ntok1) * Cdim + col;
                    v0 += Res[ri]; v1 += Res[ri + 1];
                }
                *(float2*)(Cm + (size_t)row * Nc + col) = make_float2(v0, v1);
            }
            if (row + 8 < Mr) {
                if (RES) {
                    size_t ri = ((size_t)((row + 8) / Ntok1) * Mtok + (row + 8) % Ntok1) * Cdim + col;
                    v2 += Res[ri]; v3 += Res[ri + 1];
                }
                *(float2*)(Cm + (size_t)(row + 8) * Nc + col) = make_float2(v2, v3);
            }
        }
    }
}

// ============ 64x64 tf32 mma GEMM (more blocks for deep-K / narrow-N GEMMs) ============
// 4 warps (2m x 2n), warp tile 32x32.
// GATHER: A is g_h2n; row = window slot, col = j*384+c (analytic 3x3 stride-2 gather).
// H3MAP:  C row bw -> g_h3 row (bw>>8)*257 + 1 + (bw&255).
#define PANEL64 (64 * SSTR)
template <int GATHER, int H3MAP>
__global__ void __launch_bounds__(128)
gemm_mma64(const float* __restrict__ A, const float* __restrict__ W,
           const float* __restrict__ bias, float* __restrict__ Cm,
           int Mr, int Nc, int Kd) {
    __shared__ __align__(16) float smem[4 * PANEL64];
    const int tid = threadIdx.x;
    const int wid = tid >> 5, lane = tid & 31;
    const int g = lane >> 2, t = lane & 3;
    const int wm = wid & 1, wn = wid >> 1;
    const int m0 = blockIdx.y * 64, n0 = blockIdx.x * 64;
    const int ldrow = tid >> 3, ldq = tid & 7;

    float acc[2][4][4];
    #pragma unroll
    for (int i = 0; i < 2; i++)
        #pragma unroll
        for (int j = 0; j < 4; j++)
            #pragma unroll
            for (int k = 0; k < 4; k++) acc[i][j][k] = 0.f;

    const int P = Kd >> 5;
    float4 ra[4], rb[4];

    auto ldg = [&](int p) {
        #pragma unroll
        for (int k = 0; k < 4; k++) {
            int row = ldrow + 16 * k;
            int gr = m0 + row;
            if (GATHER) {
                int b = gr >> 8, w = gr & 255;
                int wy = w >> 4, wx = w & 15;
                int j = p / 12;
                int c = (p % 12) * 32 + ldq * 4;
                int dy = j / 3 - 1, dx = j % 3 - 1;
                int rp = 2 * wy + dy, cp = 2 * wx + dx;
                int src = ((unsigned)rp < 32u && (unsigned)cp < 32u) ? (1 + rp * 32 + cp) : 1024;
                ra[k] = *(const float4*)(A + ((size_t)b * Ntok1 + src) * Cdim + c);
            } else {
                ra[k] = (gr < Mr) ? *(const float4*)(A + (size_t)gr * Kd + p * 32 + ldq * 4)
                                  : make_float4(0.f, 0.f, 0.f, 0.f);
            }
            rb[k] = *(const float4*)(W + (size_t)(n0 + row) * Kd + p * 32 + ldq * 4);
        }
    };
    auto sts = [&](int b) {
        float* Ab = smem + b * PANEL64;
        float* Bb = smem + 2 * PANEL64 + b * PANEL64;
        #pragma unroll
        for (int k = 0; k < 4; k++) {
            int row = ldrow + 16 * k;
            float4 va = ra[k], vb = rb[k];
            va.x = to_tf32(va.x); va.y = to_tf32(va.y); va.z = to_tf32(va.z); va.w = to_tf32(va.w);
            vb.x = to_tf32(vb.x); vb.y = to_tf32(vb.y); vb.z = to_tf32(vb.z); vb.w = to_tf32(vb.w);
            *(float4*)(Ab + row * SSTR + ldq * 4) = va;
            *(float4*)(Bb + row * SSTR + ldq * 4) = vb;
        }
    };
    auto compute = [&](int b) {
        const float* Ab = smem + b * PANEL64;
        const float* Bb = smem + 2 * PANEL64 + b * PANEL64;
        #pragma unroll
        for (int kk = 0; kk < 4; kk++) {
            uint32_t af[2][4];
            #pragma unroll
            for (int ma = 0; ma < 2; ma++) {
                const float* p = Ab + (wm * 32 + ma * 16 + g) * SSTR + kk * 8 + t;
                af[ma][0] = __float_as_uint(p[0]);
                af[ma][1] = __float_as_uint(p[8 * SSTR]);
                af[ma][2] = __float_as_uint(p[4]);
                af[ma][3] = __float_as_uint(p[8 * SSTR + 4]);
            }
            uint32_t bf[4][2];
            #pragma unroll
            for (int na = 0; na < 4; na++) {
                const float* p = Bb + (wn * 32 + na * 8 + g) * SSTR + kk * 8 + t;
                bf[na][0] = __float_as_uint(p[0]);
                bf[na][1] = __float_as_uint(p[4]);
            }
            #pragma unroll
            for (int ma = 0; ma < 2; ma++)
                #pragma unroll
                for (int na = 0; na < 4; na++)
                    mma_tf32(acc[ma][na], af[ma], bf[na]);
        }
    };

    ldg(0);
    sts(0);
    __syncthreads();
    for (int p = 0; p < P; p++) {
        int b = p & 1;
        if (p + 1 < P) ldg(p + 1);
        compute(b);
        __syncthreads();
        if (p + 1 < P) { sts(b ^ 1); __syncthreads(); }
    }

    #pragma unroll
    for (int ma = 0; ma < 2; ma++) {
        int row = m0 + wm * 32 + ma * 16 + g;
        #pragma unroll
        for (int na = 0; na < 4; na++) {
            int col = n0 + wn * 32 + na * 8 + 2 * t;
            float b0 = 0.f, b1 = 0.f;
            if (bias) { b0 = bias[col]; b1 = bias[col + 1]; }
            float v0 = acc[ma][na][0] + b0, v1 = acc[ma][na][1] + b1;
            float v2 = acc[ma][na][2] + b0, v3 = acc[ma][na][3] + b1;
            int r0 = row, r1 = row + 8;
            if (H3MAP) {
                int o0 = (r0 >> 8) * 257 + 1 + (r0 & 255);
                int o1 = (r1 >> 8) * 257 + 1 + (r1 & 255);
                *(float2*)(Cm + (size_t)o0 * Nc + col) = make_float2(v0, v1);
                *(float2*)(Cm + (size_t)o1 * Nc + col) = make_float2(v2, v3);
            } else {
                if (r0 < Mr) *(float2*)(Cm + (size_t)r0 * Nc + col) = make_float2(v0, v1);
                if (r1 < Mr) *(float2*)(Cm + (size_t)r1 * Nc + col) = make_float2(v2, v3);
            }
        }
    }
}

// ---------------- block reduce helper ----------------
__device__ __forceinline__ float block_reduce_sum128(float v, float* sh) {
    #pragma unroll
    for (int o = 16; o; o >>= 1) v += __shfl_xor_sync(0xffffffffu, v, o);
    int w = threadIdx.x >> 5;
    if ((threadIdx.x & 31) == 0) sh[w] = v;
    __syncthreads();
    v = sh[0] + sh[1] + sh[2] + sh[3];
    __syncthreads();
    return v;
}

__device__ __forceinline__ bool axis_ok(int a, int b) {
    int lo = max(max(a, b) - 1, 0);
    int hi = min(min(a, b) + 1, 30);
    if (lo > hi) return false;
    return ((lo & 1) == 0) || (lo + 1 <= hi);
}

// ---------------- LN1 with zero-pad row ----------------
__global__ void ln1_pad_kernel(const float* __restrict__ x,
                               const float* __restrict__ w,
                               const float* __restrict__ b) {
    __shared__ float sh[4];
    int r = blockIdx.x;
    int bb = r / Mtok, m = r % Mtok;
    int t = threadIdx.x;
    float* out = g_h + (size_t)r * Cdim;
    if (m == Ntok1) {
        out[t] = 0.f; out[t + 128] = 0.f; out[t + 256] = 0.f;
        return;
    }
    const float* xr = x + ((size_t)bb * Ntok1 + m) * Cdim;
    float v0 = xr[t], v1 = xr[t + 128], v2 = xr[t + 256];
    float mu = block_reduce_sum128(v0 + v1 + v2, sh) * (1.f / Cdim);
    float d0 = v0 - mu, d1 = v1 - mu, d2 = v2 - mu;
    float var = block_reduce_sum128(d0 * d0 + d1 * d1 + d2 * d2, sh) * (1.f / Cdim);
    float rs = rsqrtf(var + EPSLN);
    out[t]       = d0 * rs * w[t]       + b[t];
    out[t + 128] = d1 * rs * w[t + 128] + b[t + 128];
    out[t + 256] = d2 * rs * w[t + 256] + b[t + 256];
}

// ---------------- generic LN ----------------
__global__ void ln_kernel(const float* __restrict__ in,
                          const float* __restrict__ w,
                          const float* __restrict__ b,
                          float* __restrict__ out) {
    __shared__ float sh[4];
    int r = blockIdx.x, t = threadIdx.x;
    const float* xr = in + (size_t)r * Cdim;
    float v0 = xr[t], v1 = xr[t + 128], v2 = xr[t + 256];
    float mu = block_reduce_sum128(v0 + v1 + v2, sh) * (1.f / Cdim);
    float d0 = v0 - mu, d1 = v1 - mu, d2 = v2 - mu;
    float var = block_reduce_sum128(d0 * d0 + d1 * d1 + d2 * d2, sh) * (1.f / Cdim);
    float rs = rsqrtf(var + EPSLN);
    float* o = out + (size_t)r * Cdim;
    o[t]       = d0 * rs * w[t]       + b[t];
    o[t + 128] = d1 * rs * w[t + 128] + b[t + 128];
    o[t + 256] = d2 * rs * w[t + 256] + b[t + 256];
}

// ---------------- sparse attention (image queries), online softmax ----------------
// grid: (1024, Bv), block: 192 (6 warps = 6 heads). REVERTED to round-12 form
// (29 regs, occ 83%) after the two-phase variant collapsed occupancy (91 regs).
__global__ void attn_sparse_kernel() {
    int m = blockIdx.x + 1;
    int b = blockIdx.y;
    int h = threadIdx.x >> 5;
    int lane = threadIdx.x & 31;
    const float* base = g_qkv + (size_t)b * Mtok * (3 * Cdim);
    const float* qrow = base + (size_t)m * (3 * Cdim) + h * Dh;
    float q0 = qrow[lane] * SCALE, q1 = qrow[lane + 32] * SCALE;
    float mx = -1e30f, l = 0.f, a0 = 0.f, a1 = 0.f;

    auto doKey = [&](int kidx) {
        const float* kr = base + (size_t)kidx * (3 * Cdim) + Cdim + h * Dh;
        float s = q0 * kr[lane] + q1 * kr[lane + 32];
        #pragma unroll
        for (int o = 16; o; o >>= 1) s += __shfl_xor_sync(0xffffffffu, s, o);
        float mn = fmaxf(mx, s);
        float corr = __expf(mx - mn);
        float p = __expf(s - mn);
        const float* vr = base + (size_t)kidx * (3 * Cdim) + 2 * Cdim + h * Dh;
        a0 = a0 * corr + p * vr[lane];
        a1 = a1 * corr + p * vr[lane + 32];
        l = l * corr + p;
        mx = mn;
    };

    doKey(0);
    int i = m - 1, r = i >> 5, c = i & 31;
    #pragma unroll
    for (int dr = -2; dr <= 2; dr++) {
        int rp = r + dr;
        if ((unsigned)rp >= 32u || !axis_ok(r, rp)) continue;
        #pragma unroll
        for (int dc = -2; dc <= 2; dc++) {
            int cp = c + dc;
            if ((unsigned)cp >= 32u || !axis_ok(c, cp)) continue;
            doKey(1 + rp * 32 + cp);
        }
    }
    {   // padded key: score 0, v == 0
        float mn = fmaxf(mx, 0.f);
        float corr = __expf(mx - mn);
        float p = __expf(0.f - mn);
        a0 *= corr; a1 *= corr; l = l * corr + p;
    }
    float inv = 1.f / l;
    float* o = g_attn + ((size_t)(b * Ntok1 + m)) * Cdim + h * Dh;
    o[lane] = a0 * inv;
    o[lane + 32] = a1 * inv;
}

// ---------------- dense attention for CLS query ----------------
__global__ void attn_cls_kernel() {
    __shared__ float sc[Mtok];
    __shared__ float qs[Dh];
    __shared__ float red[8];
    __shared__ float accsh[256];
    int h = blockIdx.x, b = blockIdx.y;
    int tid = threadIdx.x;
    const float* base = g_qkv + (size_t)b * Mtok * (3 * Cdim);
    if (tid < Dh) qs[tid] = base[h * Dh + tid] * SCALE;
    __syncthreads();

    float lmax = -1e30f;
    for (int k = tid; k < Ntok1; k += 256) {
        const float* kr = base + (size_t)k * (3 * Cdim) + Cdim + h * Dh;
        float s = 0.f;
        #pragma unroll
        for (int d = 0; d < Dh; d++) s += qs[d] * kr[d];
        sc[k] = s;
        lmax = fmaxf(lmax, s);
    }
    if (tid == 0) sc[Ntok1] = 0.f;
    lmax = fmaxf(lmax, 0.f);
    #pragma unroll
    for (int o = 16; o; o >>= 1) lmax = fmaxf(lmax, __shfl_xor_sync(0xffffffffu, lmax, o));
    if ((tid & 31) == 0) red[tid >> 5] = lmax;
    __syncthreads();
    float mx = red[0];
    #pragma unroll
    for (int w = 1; w < 8; w++) mx = fmaxf(mx, red[w]);
    __syncthreads();

    float lsum = 0.f;
    for (int k = tid; k < Mtok; k += 256) {
        float p = __expf(sc[k] - mx);
        sc[k] = p;
        lsum += p;
    }
    #pragma unroll
    for (int o = 16; o; o >>= 1) lsum += __shfl_xor_sync(0xffffffffu, lsum, o);
    if ((tid & 31) == 0) red[tid >> 5] = lsum;
    __syncthreads();
    float Z = red[0] + red[1] + red[2] + red[3] + red[4] + red[5] + red[6] + red[7];

    int d = tid & 63, ks = tid >> 6;
    float acc = 0.f;
    for (int k = ks; k < Ntok1; k += 4)
        acc += sc[k] * base[(size_t)k * (3 * Cdim) + 2 * Cdim + h * Dh + d];
    accsh[tid] = acc;
    __syncthreads();
    if (tid < 64) {
        float o = accsh[tid] + accsh[64 + tid] + accsh[128 + tid] + accsh[192 + tid];
        g_attn[((size_t)(b * Ntok1)) * Cdim + h * Dh + tid] = o / Z;
    }
}

// ---------------- CLS row copy into g_h3 row 0 of each batch ----------------
__global__ void cls_copy_kernel() {
    int b = blockIdx.x, t = threadIdx.x;
    g_h3[(size_t)b * 257 * Cdim + t] = g_h2n[(size_t)b * Ntok1 * Cdim + t];
}

// ---------------- launch ----------------
extern "C" void kernel_launch(void* const* d_in, const int* in_sizes, int n_in,
                              void* d_out, int out_size) {
    const float* x       = (const float*)d_in[0];
    const float* norm1_w = (const float*)d_in[1];
    const float* norm1_b = (const float*)d_in[2];
    const float* qkv_w   = (const float*)d_in[3];
    const float* proj_w  = (const float*)d_in[4];
    const float* proj_b  = (const float*)d_in[5];
    const float* norm2_w = (const float*)d_in[6];
    const float* norm2_b = (const float*)d_in[7];
    const float* pool_w  = (const float*)d_in[8];
    const float* pool_b  = (const float*)d_in[9];
    const float* norm3_w = (const float*)d_in[10];
    const float* norm3_b = (const float*)d_in[11];
    const float* fc1_w   = (const float*)d_in[12];
    const float* fc1_b   = (const float*)d_in[13];
    const float* fc2_w   = (const float*)d_in[14];
    const float* fc2_b   = (const float*)d_in[15];
    float* out = (float*)d_out;

    float *p_h, *p_qkv, *p_attn, *p_h2, *p_h2n, *p_h3, *p_h3n, *p_fc1;
    cudaGetSymbolAddress((void**)&p_h,    g_h);
    cudaGetSymbolAddress((void**)&p_qkv,  g_qkv);
    cudaGetSymbolAddress((void**)&p_attn, g_attn);
    cudaGetSymbolAddress((void**)&p_h2,   g_h2);
    cudaGetSymbolAddress((void**)&p_h2n,  g_h2n);
    cudaGetSymbolAddress((void**)&p_h3,   g_h3);
    cudaGetSymbolAddress((void**)&p_h3n,  g_h3n);
    cudaGetSymbolAddress((void**)&p_fc1,  g_fc1);

    const int SMEMB = 4 * PANEL_F * sizeof(float);   // 73728 B
    cudaFuncSetAttribute(gemm_mma<0, 0>, cudaFuncAttributeMaxDynamicSharedMemorySize, SMEMB);
    cudaFuncSetAttribute(gemm_mma<0, 1>, cudaFuncAttributeMaxDynamicSharedMemorySize, SMEMB);
    cudaFuncSetAttribute(gemm_mma<1, 0>, cudaFuncAttributeMaxDynamicSharedMemorySize, SMEMB);

    // 1) LN1 + zero-pad
    ln1_pad_kernel<<<Bv * Mtok, 128>>>(x, norm1_w, norm1_b);
    // 2) QKV GEMM: (8208 x 384) @ (384 x 1152)
    gemm_mma<0, 0><<<dim3(1152 / 128, (Bv * Mtok + 127) / 128), 256, SMEMB>>>(
        p_h, qkv_w, nullptr, p_qkv, nullptr, Bv * Mtok, 3 * Cdim, Cdim);
    // 3) attention
    attn_cls_kernel<<<dim3(Hh, Bv), 256>>>();
    attn_sparse_kernel<<<dim3(NTOK, Bv), 192>>>();
    // 4) proj GEMM + fused residual add
    gemm_mma<0, 1><<<dim3(Cdim / 128, (Bv * Ntok1 + 127) / 128), 256, SMEMB>>>(
        p_attn, proj_w, proj_b, p_h2, p_h, Bv * Ntok1, Cdim, Cdim);
    // 5) LN2
    ln_kernel<<<Bv * Ntok1, 128>>>(p_h2, norm2_w, norm2_b, p_h2n);
    // 6) pool GEMM with fused gather + fused concat placement:
    //    (2048 x 3456 gathered from h2n) @ (3456 x 384) -> g_h3 rows 1..256
    gemm_mma64<1, 1><<<dim3(Cdim / 64, (Bv * WWIN) / 64), 128>>>(
        p_h2n, pool_w, pool_b, p_h3, Bv * WWIN, Cdim, 9 * Cdim);
    cls_copy_kernel<<<Bv, Cdim>>>();
    // 7) LN3
    ln_kernel<<<Bv * 257, 128>>>(p_h3, norm3_w, norm3_b, p_h3n);
    // 8) MLP
    gemm_mma<1, 0><<<dim3(HID / 128, (Bv * 257 + 127) / 128), 256, SMEMB>>>(
        p_h3n, fc1_w, fc1_b, p_fc1, nullptr, Bv * 257, HID, Cdim);
    gemm_mma64<0, 0><<<dim3(Cdim / 64, (Bv * 257 + 63) / 64), 128>>>(
        p_fc1, fc2_w, fc2_b, out, Bv * 257, Cdim, HID);
}